// round 6
// baseline (speedup 1.0000x reference)
#include <cuda_runtime.h>
#include <cuda_bf16.h>
#include <cstdint>

// d_in[0] = values     f32 [1048576, 8]
// d_in[1] = weights    f32 [65536, 8, 8]
// d_in[2] = input_idx  i32 [E]
// d_in[3] = weight_idx i32 [E]
// out     = f32 [E, 8]
//
// 8 lanes per edge, 1 edge per thread-group per iteration, persistent
// grid-stride loop, software pipelined:
//   steady state: compute iteration i with gathers issued in iteration i-1;
//   issue gathers i+1 from indices loaded in iteration i-1/i; prefetch idx i+2.
// Lane k: W float4 #k (row k>>1, col-half k&1) and #(k+8) (row (k>>1)+4),
// x half (k&1); shfl_xor(1) pair-sum; each lane stores one output element
// (pos = (k>>1) + (k&1)*4) -> warp store is 128B contiguous.

__device__ __forceinline__ float dot4(float4 a, float4 b) {
    float r = a.x * b.x;
    r = fmaf(a.y, b.y, r);
    r = fmaf(a.z, b.z, r);
    r = fmaf(a.w, b.w, r);
    return r;
}

__global__ __launch_bounds__(256) void edge_mm_kernel(
    const float4* __restrict__ values,    // [NUM_VALUES*2]  float4
    const float4* __restrict__ weights,   // [NUM_WEIGHTS*16] float4
    const int*    __restrict__ input_idx,
    const int*    __restrict__ weight_idx,
    float*        __restrict__ out,
    int E,
    int stride)                           // edges advanced per iteration
{
    int tid = blockIdx.x * blockDim.x + threadIdx.x;
    int g = tid >> 3;                     // edge id
    int k = tid & 7;                      // lane role within edge
    int half = k & 1;
    int pos = (k >> 1) + (half << 2);

    if (g >= E) return;

    // Prologue: stage-0 indices, resolve, issue stage-0 gathers
    int vi = __ldg(input_idx + g);
    int wi = __ldg(weight_idx + g);

    float4 x  = values[vi * 2 + half];
    float4 w0 = weights[wi * 16 + k];
    float4 w1 = weights[wi * 16 + k + 8];

    int gn = g + stride;
    bool more = (gn < E);
    int nvi = 0, nwi = 0;
    if (more) {
        nvi = __ldg(input_idx + gn);
        nwi = __ldg(weight_idx + gn);
    }

    while (true) {
        int g2 = gn + stride;
        bool more2 = more && (g2 < E);

        // Issue next-stage gathers (idx loaded ≥1 iteration ago)
        float4 nx  = make_float4(0.f, 0.f, 0.f, 0.f);
        float4 nw0 = nx, nw1 = nx;
        if (more) {
            nx  = values[nvi * 2 + half];
            nw0 = weights[nwi * 16 + k];
            nw1 = weights[nwi * 16 + k + 8];
        }

        // Prefetch idx two stages ahead
        int nnvi = 0, nnwi = 0;
        if (more2) {
            nnvi = __ldg(input_idx + g2);
            nnwi = __ldg(weight_idx + g2);
        }

        // Compute current stage (gathers issued last iteration)
        float p0 = dot4(w0, x);
        float p1 = dot4(w1, x);
        p0 += __shfl_xor_sync(0xFFFFFFFFu, p0, 1);
        p1 += __shfl_xor_sync(0xFFFFFFFFu, p1, 1);
        out[g * 8 + pos] = half ? p1 : p0;

        if (!more) break;
        g = gn; gn = g2; more = more2;
        x = nx; w0 = nw0; w1 = nw1;
        nvi = nnvi; nwi = nnwi;
    }
}

extern "C" void kernel_launch(void* const* d_in, const int* in_sizes, int n_in,
                              void* d_out, int out_size)
{
    const float4* values  = (const float4*)d_in[0];
    const float4* weights = (const float4*)d_in[1];
    const int* input_idx  = (const int*)d_in[2];
    const int* weight_idx = (const int*)d_in[3];
    float* out = (float*)d_out;

    int E = in_sizes[2];                  // 4194304

    int threads = 256;
    int blocks = 2048;                    // persistent-style launch
    long long needed = ((long long)E * 8 + threads - 1) / threads;
    if (needed < blocks) blocks = (int)needed;
    int stride = blocks * (threads >> 3); // edges per sweep (65536)

    edge_mm_kernel<<<blocks, threads>>>(values, weights, input_idx, weight_idx,
                                        out, E, stride);
}

// round 8
// speedup vs baseline: 1.4851x; 1.4851x over previous
#include <cuda_runtime.h>
#include <cuda_bf16.h>
#include <cstdint>

// d_in[0] = values     f32 [1048576, 8]
// d_in[1] = weights    f32 [65536, 8, 8]
// d_in[2] = input_idx  i32 [E]
// d_in[3] = weight_idx i32 [E]
// out     = f32 [E, 8]
//
// 8 lanes per edge; lane k owns output row k. Blackwell 256-bit loads:
//   - lane k loads the full 32B W row k (8 lanes -> 256B contiguous, full
//     line coverage, no shuffles needed)
//   - every lane loads the full 32B x row (same address across the edge's
//     8 lanes -> merged broadcast)
// 2 independent edge chains (e, e+E/2), persistent grid-stride loop with
// next-iteration idx prefetch (R4 skeleton, best so far).
// Cache policy: gathers L2::evict_last (pin 48MB reuse set), idx __ldcs,
// stores __stcs (streaming, never reused).

__device__ __forceinline__ void ldg256_el(const float* p, float r[8]) {
    unsigned u0, u1, u2, u3, u4, u5, u6, u7;
    asm("ld.global.nc.L2::evict_last.v8.b32 {%0,%1,%2,%3,%4,%5,%6,%7}, [%8];"
        : "=r"(u0), "=r"(u1), "=r"(u2), "=r"(u3),
          "=r"(u4), "=r"(u5), "=r"(u6), "=r"(u7)
        : "l"(p));
    r[0] = __uint_as_float(u0); r[1] = __uint_as_float(u1);
    r[2] = __uint_as_float(u2); r[3] = __uint_as_float(u3);
    r[4] = __uint_as_float(u4); r[5] = __uint_as_float(u5);
    r[6] = __uint_as_float(u6); r[7] = __uint_as_float(u7);
}

__device__ __forceinline__ float dot8(const float w[8], const float x[8]) {
    float r = w[0] * x[0];
    r = fmaf(w[1], x[1], r);
    r = fmaf(w[2], x[2], r);
    r = fmaf(w[3], x[3], r);
    r = fmaf(w[4], x[4], r);
    r = fmaf(w[5], x[5], r);
    r = fmaf(w[6], x[6], r);
    r = fmaf(w[7], x[7], r);
    return r;
}

__global__ __launch_bounds__(256) void edge_mm_kernel(
    const float* __restrict__ values,     // [1048576*8]
    const float* __restrict__ weights,    // [65536*64]
    const int*   __restrict__ input_idx,
    const int*   __restrict__ weight_idx,
    float*       __restrict__ out,
    int half_E,
    int group_stride)                     // edge-groups advanced per iteration
{
    int tid = blockIdx.x * blockDim.x + threadIdx.x;
    int g = tid >> 3;                     // edge id (chain 0)
    int k = tid & 7;                      // output row owned by this lane

    if (g >= half_E) return;

    // Prologue: indices for the first group (streaming loads)
    int vi0 = __ldcs(input_idx + g);
    int wi0 = __ldcs(weight_idx + g);
    int vi1 = __ldcs(input_idx + g + half_E);
    int wi1 = __ldcs(weight_idx + g + half_E);

    while (true) {
        int gn = g + group_stride;
        bool more = (gn < half_E);

        // Gathers for the current pair of edges (32B each, evict_last)
        float x0[8], x1[8], w0[8], w1[8];
        ldg256_el(values + vi0 * 8, x0);
        ldg256_el(values + vi1 * 8, x1);
        ldg256_el(weights + wi0 * 64 + k * 8, w0);
        ldg256_el(weights + wi1 * 64 + k * 8, w1);

        // Prefetch next iteration's indices — overlaps gather latency
        int nvi0 = 0, nwi0 = 0, nvi1 = 0, nwi1 = 0;
        if (more) {
            nvi0 = __ldcs(input_idx + gn);
            nwi0 = __ldcs(weight_idx + gn);
            nvi1 = __ldcs(input_idx + gn + half_E);
            nwi1 = __ldcs(weight_idx + gn + half_E);
        }

        float y0 = dot8(w0, x0);
        float y1 = dot8(w1, x1);

        __stcs(out + g * 8 + k, y0);
        __stcs(out + (g + half_E) * 8 + k, y1);

        if (!more) break;
        g = gn;
        vi0 = nvi0; wi0 = nwi0; vi1 = nvi1; wi1 = nwi1;
    }
}

extern "C" void kernel_launch(void* const* d_in, const int* in_sizes, int n_in,
                              void* d_out, int out_size)
{
    const float* values  = (const float*)d_in[0];
    const float* weights = (const float*)d_in[1];
    const int* input_idx  = (const int*)d_in[2];
    const int* weight_idx = (const int*)d_in[3];
    float* out = (float*)d_out;

    int E = in_sizes[2];
    int half_E = E >> 1;                  // E even (4194304)

    int threads = 256;
    int blocks = 2048;
    long long needed = ((long long)half_E * 8 + threads - 1) / threads;
    if (needed < blocks) blocks = (int)needed;
    int groups_per_iter = blocks * (threads >> 3);

    edge_mm_kernel<<<blocks, threads>>>(values, weights, input_idx, weight_idx,
                                        out, half_E, groups_per_iter);
}

// round 9
// speedup vs baseline: 1.6186x; 1.0899x over previous
#include <cuda_runtime.h>
#include <cuda_bf16.h>
#include <cstdint>

// d_in[0] = values     f32 [1048576, 8]
// d_in[1] = weights    f32 [65536, 8, 8]
// d_in[2] = input_idx  i32 [E]
// d_in[3] = weight_idx i32 [E]
// out     = f32 [E, 8]
//
// R4 structure (best: 88.6us): 8 lanes/edge, 2 edge chains (e, e+E/2),
// persistent grid-stride loop with next-iteration idx prefetch.
// Lane k: W float4 #k and #(k+8) (full 128B line coverage); x half (k&1);
// shfl_xor(1) pair-sum; lane stores one element (pos=(k>>1)+(k&1)*4).
//
// R8 adds cache policy in its LEGAL form:
//   - values/weights gathers: createpolicy L2::evict_last + ld...L2::cache_hint
//     (pins the 48MB values+weights reuse set in the 126MB L2 against the
//      ~160MB/launch of streaming idx+out traffic)
//   - idx loads: __ldcs (evict-first), out stores: __stcs (write-once)

__device__ __forceinline__ float4 ldg_el(const float4* p, uint64_t pol) {
    float4 v;
    asm("ld.global.nc.L2::cache_hint.v4.f32 {%0,%1,%2,%3}, [%4], %5;"
        : "=f"(v.x), "=f"(v.y), "=f"(v.z), "=f"(v.w)
        : "l"(p), "l"(pol));
    return v;
}

__device__ __forceinline__ float dot4(float4 a, float4 b) {
    float r = a.x * b.x;
    r = fmaf(a.y, b.y, r);
    r = fmaf(a.z, b.z, r);
    r = fmaf(a.w, b.w, r);
    return r;
}

__global__ __launch_bounds__(256) void edge_mm_kernel(
    const float4* __restrict__ values,    // [NUM_VALUES*2]  float4
    const float4* __restrict__ weights,   // [NUM_WEIGHTS*16] float4
    const int*    __restrict__ input_idx,
    const int*    __restrict__ weight_idx,
    float*        __restrict__ out,
    int half_E,
    int group_stride)                     // groups advanced per iteration
{
    int tid = blockIdx.x * blockDim.x + threadIdx.x;
    int g = tid >> 3;                     // edge-group id
    int k = tid & 7;                      // lane role within edge
    int half = k & 1;
    int pos = (k >> 1) + (half << 2);

    if (g >= half_E) return;

    uint64_t pol;
    asm("createpolicy.fractional.L2::evict_last.b64 %0, 1.0;" : "=l"(pol));

    // Prologue: indices for the first group (streaming loads)
    int vi0 = __ldcs(input_idx + g);
    int wi0 = __ldcs(weight_idx + g);
    int vi1 = __ldcs(input_idx + g + half_E);
    int wi1 = __ldcs(weight_idx + g + half_E);

    while (true) {
        int gn = g + group_stride;
        bool more = (gn < half_E);

        // Issue current gathers (idx already resolved) — evict_last hint
        float4 xa = ldg_el(values + vi0 * 2 + half, pol);
        float4 xb = ldg_el(values + vi1 * 2 + half, pol);
        const float4* W0 = weights + wi0 * 16;
        const float4* W1 = weights + wi1 * 16;
        float4 wa0 = ldg_el(W0 + k, pol);
        float4 wa1 = ldg_el(W0 + k + 8, pol);
        float4 wb0 = ldg_el(W1 + k, pol);
        float4 wb1 = ldg_el(W1 + k + 8, pol);

        // Prefetch next iteration's indices — overlaps gather latency
        int nvi0 = 0, nwi0 = 0, nvi1 = 0, nwi1 = 0;
        if (more) {
            nvi0 = __ldcs(input_idx + gn);
            nwi0 = __ldcs(weight_idx + gn);
            nvi1 = __ldcs(input_idx + gn + half_E);
            nwi1 = __ldcs(weight_idx + gn + half_E);
        }

        // Compute
        float pa0 = dot4(wa0, xa);
        float pa1 = dot4(wa1, xa);
        float pb0 = dot4(wb0, xb);
        float pb1 = dot4(wb1, xb);

        pa0 += __shfl_xor_sync(0xFFFFFFFFu, pa0, 1);
        pa1 += __shfl_xor_sync(0xFFFFFFFFu, pa1, 1);
        pb0 += __shfl_xor_sync(0xFFFFFFFFu, pb0, 1);
        pb1 += __shfl_xor_sync(0xFFFFFFFFu, pb1, 1);

        float ya = half ? pa1 : pa0;
        float yb = half ? pb1 : pb0;

        __stcs(out + g * 8 + pos, ya);
        __stcs(out + (g + half_E) * 8 + pos, yb);

        if (!more) break;
        g = gn;
        vi0 = nvi0; wi0 = nwi0; vi1 = nvi1; wi1 = nwi1;
    }
}

extern "C" void kernel_launch(void* const* d_in, const int* in_sizes, int n_in,
                              void* d_out, int out_size)
{
    const float4* values  = (const float4*)d_in[0];
    const float4* weights = (const float4*)d_in[1];
    const int* input_idx  = (const int*)d_in[2];
    const int* weight_idx = (const int*)d_in[3];
    float* out = (float*)d_out;

    int E = in_sizes[2];
    int half_E = E >> 1;                  // E even (4194304)

    int threads = 256;
    int blocks = 2048;
    long long needed = ((long long)half_E * 8 + threads - 1) / threads;
    if (needed < blocks) blocks = (int)needed;
    int groups_per_iter = blocks * (threads >> 3);

    edge_mm_kernel<<<blocks, threads>>>(values, weights, input_idx, weight_idx,
                                        out, half_E, groups_per_iter);
}

// round 10
// speedup vs baseline: 1.6660x; 1.0293x over previous
#include <cuda_runtime.h>
#include <cuda_bf16.h>
#include <cstdint>

// d_in[0] = values     f32 [1048576, 8]
// d_in[1] = weights    f32 [65536, 8, 8]
// d_in[2] = input_idx  i32 [E]
// d_in[3] = weight_idx i32 [E]
// out     = f32 [E, 8]
//
// 8 lanes/edge, 2 edge chains (e, e+half_E), persistent warp-stride loop.
// R9: warp-batched idx loads — every 8 inner iterations, the warp loads 32
// consecutive input_idx/weight_idx per chain with 4 fully-coalesced 128B
// loads (4 wf / 64 edges vs 32 wf before), distributed via shfl.idx.
// Inner iteration identical to R4/R8: lane k takes W float4 #k and #(k+8)
// (full 128B line coverage), x half (k&1), shfl_xor(1) pair-sum, lane stores
// one element at pos=(k>>1)+(k&1)*4 (warp store = contiguous 128B).
// Cache policy (R8 win): gathers L2::evict_last, idx __ldcs, stores __stcs.

__device__ __forceinline__ float4 ldg_el(const float4* p, uint64_t pol) {
    float4 v;
    asm("ld.global.nc.L2::cache_hint.v4.f32 {%0,%1,%2,%3}, [%4], %5;"
        : "=f"(v.x), "=f"(v.y), "=f"(v.z), "=f"(v.w)
        : "l"(p), "l"(pol));
    return v;
}

__device__ __forceinline__ float dot4(float4 a, float4 b) {
    float r = a.x * b.x;
    r = fmaf(a.y, b.y, r);
    r = fmaf(a.z, b.z, r);
    r = fmaf(a.w, b.w, r);
    return r;
}

__global__ __launch_bounds__(256) void edge_mm_kernel(
    const float4* __restrict__ values,    // [NUM_VALUES*2]  float4
    const float4* __restrict__ weights,   // [NUM_WEIGHTS*16] float4
    const int*    __restrict__ input_idx,
    const int*    __restrict__ weight_idx,
    float*        __restrict__ out,
    int half_E,
    int nfull)                            // half_E rounded down to 32
{
    int tid = blockIdx.x * blockDim.x + threadIdx.x;
    int lane = threadIdx.x & 31;
    int warpG = tid >> 5;
    int totalWarps = (gridDim.x * blockDim.x) >> 5;
    int k = lane & 7;                     // lane role within edge
    int grp = lane >> 3;                  // edge slot within inner iteration
    int half = k & 1;
    int pos = (k >> 1) + (half << 2);

    uint64_t pol;
    asm("createpolicy.fractional.L2::evict_last.b64 %0, 1.0;" : "=l"(pol));

    for (int base = warpG * 32; base < nfull; base += totalWarps * 32) {
        // Coalesced idx batch: 32 edges per chain, 4 x 128B loads
        int inA = __ldcs(input_idx + base + lane);
        int wA  = __ldcs(weight_idx + base + lane);
        int inB = __ldcs(input_idx + base + half_E + lane);
        int wB  = __ldcs(weight_idx + base + half_E + lane);

#pragma unroll 1
        for (int j = 0; j < 8; j++) {
            int src = j * 4 + grp;
            int vi0 = __shfl_sync(0xFFFFFFFFu, inA, src);
            int wi0 = __shfl_sync(0xFFFFFFFFu, wA, src);
            int vi1 = __shfl_sync(0xFFFFFFFFu, inB, src);
            int wi1 = __shfl_sync(0xFFFFFFFFu, wB, src);

            float4 xa = ldg_el(values + vi0 * 2 + half, pol);
            float4 xb = ldg_el(values + vi1 * 2 + half, pol);
            const float4* W0 = weights + wi0 * 16;
            const float4* W1 = weights + wi1 * 16;
            float4 wa0 = ldg_el(W0 + k, pol);
            float4 wa1 = ldg_el(W0 + k + 8, pol);
            float4 wb0 = ldg_el(W1 + k, pol);
            float4 wb1 = ldg_el(W1 + k + 8, pol);

            float pa0 = dot4(wa0, xa);
            float pa1 = dot4(wa1, xa);
            float pb0 = dot4(wb0, xb);
            float pb1 = dot4(wb1, xb);

            pa0 += __shfl_xor_sync(0xFFFFFFFFu, pa0, 1);
            pa1 += __shfl_xor_sync(0xFFFFFFFFu, pa1, 1);
            pb0 += __shfl_xor_sync(0xFFFFFFFFu, pb0, 1);
            pb1 += __shfl_xor_sync(0xFFFFFFFFu, pb1, 1);

            int e0 = base + src;
            __stcs(out + e0 * 8 + pos, half ? pa1 : pa0);
            __stcs(out + (e0 + half_E) * 8 + pos, half ? pb1 : pb0);
        }
    }

    // Tail (half_E % 32 != 0; never taken for E = 4194304)
    int e = nfull + (tid >> 3);
    if (e < half_E) {
        int vi0 = __ldg(input_idx + e);
        int wi0 = __ldg(weight_idx + e);
        int vi1 = __ldg(input_idx + e + half_E);
        int wi1 = __ldg(weight_idx + e + half_E);
        float4 xa = ldg_el(values + vi0 * 2 + half, pol);
        float4 xb = ldg_el(values + vi1 * 2 + half, pol);
        float4 wa0 = ldg_el(weights + wi0 * 16 + k, pol);
        float4 wa1 = ldg_el(weights + wi0 * 16 + k + 8, pol);
        float4 wb0 = ldg_el(weights + wi1 * 16 + k, pol);
        float4 wb1 = ldg_el(weights + wi1 * 16 + k + 8, pol);
        float pa0 = dot4(wa0, xa);
        float pa1 = dot4(wa1, xa);
        float pb0 = dot4(wb0, xb);
        float pb1 = dot4(wb1, xb);
        pa0 += __shfl_xor_sync(0xFFFFFFFFu, pa0, 1);
        pa1 += __shfl_xor_sync(0xFFFFFFFFu, pa1, 1);
        pb0 += __shfl_xor_sync(0xFFFFFFFFu, pb0, 1);
        pb1 += __shfl_xor_sync(0xFFFFFFFFu, pb1, 1);
        __stcs(out + e * 8 + pos, half ? pa1 : pa0);
        __stcs(out + (e + half_E) * 8 + pos, half ? pb1 : pb0);
    }
}

extern "C" void kernel_launch(void* const* d_in, const int* in_sizes, int n_in,
                              void* d_out, int out_size)
{
    const float4* values  = (const float4*)d_in[0];
    const float4* weights = (const float4*)d_in[1];
    const int* input_idx  = (const int*)d_in[2];
    const int* weight_idx = (const int*)d_in[3];
    float* out = (float*)d_out;

    int E = in_sizes[2];
    int half_E = E >> 1;                  // E even (4194304)
    int nfull = half_E & ~31;

    int threads = 256;
    int blocks = 2048;
    long long needed = ((long long)half_E * 8 + threads - 1) / threads;
    if (needed < blocks) blocks = (int)needed;

    edge_mm_kernel<<<blocks, threads>>>(values, weights, input_idx, weight_idx,
                                        out, half_E, nfull);
}

// round 11
// speedup vs baseline: 1.7989x; 1.0798x over previous
#include <cuda_runtime.h>
#include <cuda_bf16.h>
#include <cstdint>

// d_in[0] = values     f32 [1048576, 8]
// d_in[1] = weights    f32 [65536, 8, 8]
// d_in[2] = input_idx  i32 [E]
// d_in[3] = weight_idx i32 [E]
// out     = f32 [E, 8]
//
// R9 skeleton: 8 lanes/edge, 2 edge chains (e, e+half_E), warp-batched
// coalesced idx loads (4 x 128B per 64 edges) distributed via shfl.idx,
// evict_last gathers, __stcs streaming stores.
// R10 changes:
//   (1) single-shfl pair reduction: each lane sends the partial its xor-1
//       partner needs (even sends p1, odd sends p0) -> 1 shfl per chain
//       instead of 2 (shfl shares the L1tex/MIO pipe with the gathers).
//   (2) balanced resident grid: exactly 148*8 = 1184 CTAs, single wave,
//       __launch_bounds__(256,8) pins regs <= 32 so all are resident.

__device__ __forceinline__ float4 ldg_el(const float4* p, uint64_t pol) {
    float4 v;
    asm("ld.global.nc.L2::cache_hint.v4.f32 {%0,%1,%2,%3}, [%4], %5;"
        : "=f"(v.x), "=f"(v.y), "=f"(v.z), "=f"(v.w)
        : "l"(p), "l"(pol));
    return v;
}

__device__ __forceinline__ float dot4(float4 a, float4 b) {
    float r = a.x * b.x;
    r = fmaf(a.y, b.y, r);
    r = fmaf(a.z, b.z, r);
    r = fmaf(a.w, b.w, r);
    return r;
}

__global__ __launch_bounds__(256, 8) void edge_mm_kernel(
    const float4* __restrict__ values,    // [NUM_VALUES*2]  float4
    const float4* __restrict__ weights,   // [NUM_WEIGHTS*16] float4
    const int*    __restrict__ input_idx,
    const int*    __restrict__ weight_idx,
    float*        __restrict__ out,
    int half_E,
    int nfull)                            // half_E rounded down to 32
{
    int tid = blockIdx.x * blockDim.x + threadIdx.x;
    int lane = threadIdx.x & 31;
    int warpG = tid >> 5;
    int totalWarps = (gridDim.x * blockDim.x) >> 5;
    int k = lane & 7;                     // lane role within edge
    int grp = lane >> 3;                  // edge slot within inner iteration
    int half = k & 1;
    int pos = (k >> 1) + (half << 2);

    uint64_t pol;
    asm("createpolicy.fractional.L2::evict_last.b64 %0, 1.0;" : "=l"(pol));

    for (int base = warpG * 32; base < nfull; base += totalWarps * 32) {
        // Coalesced idx batch: 32 edges per chain, 4 x 128B loads
        int inA = __ldcs(input_idx + base + lane);
        int wA  = __ldcs(weight_idx + base + lane);
        int inB = __ldcs(input_idx + base + half_E + lane);
        int wB  = __ldcs(weight_idx + base + half_E + lane);

#pragma unroll 1
        for (int j = 0; j < 8; j++) {
            int src = j * 4 + grp;
            int vi0 = __shfl_sync(0xFFFFFFFFu, inA, src);
            int wi0 = __shfl_sync(0xFFFFFFFFu, wA, src);
            int vi1 = __shfl_sync(0xFFFFFFFFu, inB, src);
            int wi1 = __shfl_sync(0xFFFFFFFFu, wB, src);

            float4 xa = ldg_el(values + vi0 * 2 + half, pol);
            float4 xb = ldg_el(values + vi1 * 2 + half, pol);
            const float4* W0 = weights + wi0 * 16;
            const float4* W1 = weights + wi1 * 16;
            float4 wa0 = ldg_el(W0 + k, pol);
            float4 wa1 = ldg_el(W0 + k + 8, pol);
            float4 wb0 = ldg_el(W1 + k, pol);
            float4 wb1 = ldg_el(W1 + k + 8, pol);

            float pa0 = dot4(wa0, xa);
            float pa1 = dot4(wa1, xa);
            float pb0 = dot4(wb0, xb);
            float pb1 = dot4(wb1, xb);

            // Single-shfl pair reduction: send what the partner needs.
            // even (half=0) keeps p0 (row k>>1), needs partner p0, sends p1
            // odd  (half=1) keeps p1 (row (k>>1)+4), needs partner p1, sends p0
            float sendA = half ? pa0 : pa1;
            float sendB = half ? pb0 : pb1;
            float recvA = __shfl_xor_sync(0xFFFFFFFFu, sendA, 1);
            float recvB = __shfl_xor_sync(0xFFFFFFFFu, sendB, 1);
            float ya = (half ? pa1 : pa0) + recvA;
            float yb = (half ? pb1 : pb0) + recvB;

            int e0 = base + src;
            __stcs(out + e0 * 8 + pos, ya);
            __stcs(out + (e0 + half_E) * 8 + pos, yb);
        }
    }

    // Tail (half_E % 32 != 0; never taken for E = 4194304)
    int e = nfull + (tid >> 3);
    if (e < half_E) {
        int vi0 = __ldg(input_idx + e);
        int wi0 = __ldg(weight_idx + e);
        int vi1 = __ldg(input_idx + e + half_E);
        int wi1 = __ldg(weight_idx + e + half_E);
        float4 xa = ldg_el(values + vi0 * 2 + half, pol);
        float4 xb = ldg_el(values + vi1 * 2 + half, pol);
        float4 wa0 = ldg_el(weights + wi0 * 16 + k, pol);
        float4 wa1 = ldg_el(weights + wi0 * 16 + k + 8, pol);
        float4 wb0 = ldg_el(weights + wi1 * 16 + k, pol);
        float4 wb1 = ldg_el(weights + wi1 * 16 + k + 8, pol);
        float pa0 = dot4(wa0, xa);
        float pa1 = dot4(wa1, xa);
        float pb0 = dot4(wb0, xb);
        float pb1 = dot4(wb1, xb);
        float sendA = half ? pa0 : pa1;
        float sendB = half ? pb0 : pb1;
        float recvA = __shfl_xor_sync(0xFFFFFFFFu, sendA, 1);
        float recvB = __shfl_xor_sync(0xFFFFFFFFu, sendB, 1);
        __stcs(out + e * 8 + pos, (half ? pa1 : pa0) + recvA);
        __stcs(out + (e + half_E) * 8 + pos, (half ? pb1 : pb0) + recvB);
    }
}

extern "C" void kernel_launch(void* const* d_in, const int* in_sizes, int n_in,
                              void* d_out, int out_size)
{
    const float4* values  = (const float4*)d_in[0];
    const float4* weights = (const float4*)d_in[1];
    const int* input_idx  = (const int*)d_in[2];
    const int* weight_idx = (const int*)d_in[3];
    float* out = (float*)d_out;

    int E = in_sizes[2];
    int half_E = E >> 1;                  // E even (4194304)
    int nfull = half_E & ~31;

    int threads = 256;
    int blocks = 1184;                    // 148 SMs * 8 resident CTAs
    long long needed = ((long long)half_E * 8 + threads - 1) / threads;
    if (needed < blocks) blocks = (int)needed;

    edge_mm_kernel<<<blocks, threads>>>(values, weights, input_idx, weight_idx,
                                        out, half_E, nfull);
}

// round 12
// speedup vs baseline: 1.8554x; 1.0314x over previous
#include <cuda_runtime.h>
#include <cuda_bf16.h>
#include <cstdint>

// d_in[0] = values     f32 [1048576, 8]
// d_in[1] = weights    f32 [65536, 8, 8]
// d_in[2] = input_idx  i32 [E]
// d_in[3] = weight_idx i32 [E]
// out     = f32 [E, 8]
//
// R10 skeleton (best: 77.8us): 8 lanes/edge, 2 edge chains (e, e+half_E),
// warp-batched coalesced idx loads distributed via shfl.idx, single-shfl
// pair reduction, evict_last gathers, __stcs stores, 1184-CTA single wave,
// __launch_bounds__(256,8) pinning 32 regs.
// R11: weight_idx < 65536 -> pack (wA | wB<<16) once per batch and
// distribute both chains' weight indices with ONE shfl (idx shfls 4 -> 3
// per inner iteration; shfl shares the MIO pipe with the gathers).

__device__ __forceinline__ float4 ldg_el(const float4* p, uint64_t pol) {
    float4 v;
    asm("ld.global.nc.L2::cache_hint.v4.f32 {%0,%1,%2,%3}, [%4], %5;"
        : "=f"(v.x), "=f"(v.y), "=f"(v.z), "=f"(v.w)
        : "l"(p), "l"(pol));
    return v;
}

__device__ __forceinline__ float dot4(float4 a, float4 b) {
    float r = a.x * b.x;
    r = fmaf(a.y, b.y, r);
    r = fmaf(a.z, b.z, r);
    r = fmaf(a.w, b.w, r);
    return r;
}

__global__ __launch_bounds__(256, 8) void edge_mm_kernel(
    const float4* __restrict__ values,    // [NUM_VALUES*2]  float4
    const float4* __restrict__ weights,   // [NUM_WEIGHTS*16] float4
    const int*    __restrict__ input_idx,
    const int*    __restrict__ weight_idx,
    float*        __restrict__ out,
    int half_E,
    int nfull)                            // half_E rounded down to 32
{
    int tid = blockIdx.x * blockDim.x + threadIdx.x;
    int lane = threadIdx.x & 31;
    int warpG = tid >> 5;
    int totalWarps = (gridDim.x * blockDim.x) >> 5;
    int k = lane & 7;                     // lane role within edge
    int grp = lane >> 3;                  // edge slot within inner iteration
    int half = k & 1;
    int pos = (k >> 1) + (half << 2);

    uint64_t pol;
    asm("createpolicy.fractional.L2::evict_last.b64 %0, 1.0;" : "=l"(pol));

    for (int base = warpG * 32; base < nfull; base += totalWarps * 32) {
        // Coalesced idx batch: 32 edges per chain, 4 x 128B loads.
        int inA = __ldcs(input_idx + base + lane);
        int wA  = __ldcs(weight_idx + base + lane);
        int inB = __ldcs(input_idx + base + half_E + lane);
        int wB  = __ldcs(weight_idx + base + half_E + lane);
        // weight_idx < 65536: pack both chains' weight idx into one register
        unsigned wAB = (unsigned)wA | ((unsigned)wB << 16);

#pragma unroll 1
        for (int j = 0; j < 8; j++) {
            int src = j * 4 + grp;
            int vi0 = __shfl_sync(0xFFFFFFFFu, inA, src);
            int vi1 = __shfl_sync(0xFFFFFFFFu, inB, src);
            unsigned wp = __shfl_sync(0xFFFFFFFFu, wAB, src);
            int wi0 = (int)(wp & 0xFFFFu);
            int wi1 = (int)(wp >> 16);

            float4 xa = ldg_el(values + vi0 * 2 + half, pol);
            float4 xb = ldg_el(values + vi1 * 2 + half, pol);
            const float4* W0 = weights + wi0 * 16;
            const float4* W1 = weights + wi1 * 16;
            float4 wa0 = ldg_el(W0 + k, pol);
            float4 wa1 = ldg_el(W0 + k + 8, pol);
            float4 wb0 = ldg_el(W1 + k, pol);
            float4 wb1 = ldg_el(W1 + k + 8, pol);

            float pa0 = dot4(wa0, xa);
            float pa1 = dot4(wa1, xa);
            float pb0 = dot4(wb0, xb);
            float pb1 = dot4(wb1, xb);

            // Single-shfl pair reduction: send what the xor-1 partner needs.
            float sendA = half ? pa0 : pa1;
            float sendB = half ? pb0 : pb1;
            float recvA = __shfl_xor_sync(0xFFFFFFFFu, sendA, 1);
            float recvB = __shfl_xor_sync(0xFFFFFFFFu, sendB, 1);
            float ya = (half ? pa1 : pa0) + recvA;
            float yb = (half ? pb1 : pb0) + recvB;

            int e0 = base + src;
            __stcs(out + e0 * 8 + pos, ya);
            __stcs(out + (e0 + half_E) * 8 + pos, yb);
        }
    }

    // Tail (half_E % 32 != 0; never taken for E = 4194304)
    int e = nfull + (tid >> 3);
    if (e < half_E) {
        int vi0 = __ldg(input_idx + e);
        int wi0 = __ldg(weight_idx + e);
        int vi1 = __ldg(input_idx + e + half_E);
        int wi1 = __ldg(weight_idx + e + half_E);
        float4 xa = ldg_el(values + vi0 * 2 + half, pol);
        float4 xb = ldg_el(values + vi1 * 2 + half, pol);
        float4 wa0 = ldg_el(weights + wi0 * 16 + k, pol);
        float4 wa1 = ldg_el(weights + wi0 * 16 + k + 8, pol);
        float4 wb0 = ldg_el(weights + wi1 * 16 + k, pol);
        float4 wb1 = ldg_el(weights + wi1 * 16 + k + 8, pol);
        float pa0 = dot4(wa0, xa);
        float pa1 = dot4(wa1, xa);
        float pb0 = dot4(wb0, xb);
        float pb1 = dot4(wb1, xb);
        float sendA = half ? pa0 : pa1;
        float sendB = half ? pb0 : pb1;
        float recvA = __shfl_xor_sync(0xFFFFFFFFu, sendA, 1);
        float recvB = __shfl_xor_sync(0xFFFFFFFFu, sendB, 1);
        __stcs(out + e * 8 + pos, (half ? pa1 : pa0) + recvA);
        __stcs(out + (e + half_E) * 8 + pos, (half ? pb1 : pb0) + recvB);
    }
}

extern "C" void kernel_launch(void* const* d_in, const int* in_sizes, int n_in,
                              void* d_out, int out_size)
{
    const float4* values  = (const float4*)d_in[0];
    const float4* weights = (const float4*)d_in[1];
    const int* input_idx  = (const int*)d_in[2];
    const int* weight_idx = (const int*)d_in[3];
    float* out = (float*)d_out;

    int E = in_sizes[2];
    int half_E = E >> 1;                  // E even (4194304)
    int nfull = half_E & ~31;

    int threads = 256;
    int blocks = 1184;                    // 148 SMs * 8 resident CTAs
    long long needed = ((long long)half_E * 8 + threads - 1) / threads;
    if (needed < blocks) blocks = (int)needed;

    edge_mm_kernel<<<blocks, threads>>>(values, weights, input_idx, weight_idx,
                                        out, half_E, nfull);
}